// round 7
// baseline (speedup 1.0000x reference)
#include <cuda_runtime.h>
#include <cuda_bf16.h>
#include <math.h>

// Problem constants (fixed by reference)
#define B_      16
#define T_      8192
#define D_      512
#define H_      8
#define HD_     64
#define K_      4
#define TROWS_  16
#define TB_     (T_/TROWS_)       // 512 tiles per batch
#define TSTRIDE_ 516
#define NTHR_   256
#define NBUF_   3

// Exactly one wave: 2 CTAs/SM x 152 SMs = 304 = 16 batches x 19 CTAs.
#define GB_     19
#define G_      (B_*GB_)          // 304

#define SM_TILE_F (TROWS_*TSTRIDE_)   // 8256 floats per buffer
#define SM_Q_F    (K_*D_)             // 2048
#define SM_P_F    (H_*TROWS_*K_)      // 512
#define SMEM_BYTES ((NBUF_*SM_TILE_F + SM_Q_F + SM_P_F)*4 + NBUF_*TROWS_*4)

// ---------------- device scratch (no allocations allowed) ----------------
__device__ __align__(16) float g_pool[B_*K_*D_];     // atomic accumulators
__device__ __align__(16) float g_lsum[B_*K_*H_];     // atomic denominators

// ---------------- packed fp32x2 FMA (Blackwell) ----------------
union F2U { float2 f; unsigned long long u; };
__device__ __forceinline__ float2 ffma2(float2 a, float2 b, float2 c) {
    F2U A, Bv, C, Dv;
    A.f = a; Bv.f = b; C.f = c;
    asm("fma.rn.f32x2 %0, %1, %2, %3;" : "=l"(Dv.u) : "l"(A.u), "l"(Bv.u), "l"(C.u));
    return Dv.f;
}

#define CP_COMMIT() asm volatile("cp.async.commit_group;")
#define CP_WAIT1()  asm volatile("cp.async.wait_group 1;")
#define CP_WAIT0()  asm volatile("cp.async.wait_group 0;")

__device__ __forceinline__ void cp16(float* dst_sh, const void* src) {
    unsigned d = (unsigned)__cvta_generic_to_shared(dst_sh);
    asm volatile("cp.async.cg.shared.global [%0], [%1], 16;" :: "r"(d), "l"(src));
}

// issue one 16x512 tile (+16 mask ints) into a buffer via cp.async
__device__ __forceinline__ void issue_tile(const float* __restrict__ src,
                                           float* __restrict__ dst,
                                           const int* __restrict__ msrc,
                                           int* __restrict__ mdst, int tid)
{
    #pragma unroll
    for (int it = 0; it < 8; it++) {
        int f   = tid + NTHR_ * it;     // 0..2047
        int row = f >> 7;               // 0..15
        int c4  = f & 127;
        cp16(dst + row * TSTRIDE_ + c4 * 4, src + (long)row * D_ + c4 * 4);
    }
    if (tid < 4) cp16((float*)(mdst + tid * 4), msrc + tid * 4);
}

// ======================================================================
// Kernel 0: zero the atomic accumulators
// ======================================================================
__global__ void zero_k()
{
    int i = blockIdx.x * 256 + threadIdx.x;
    if (i < B_*K_*D_) g_pool[i] = 0.f;
    if (i < B_*K_*H_) g_lsum[i] = 0.f;
}

// ======================================================================
// Kernel 1: pipelined attention pooling, fixed softmax shift (m = 0).
// R3-proven mainloop: NBUF=3, one __syncthreads per tile, q in SMEM,
// 2 CTAs/SM. Grid = exactly one balanced wave (16 x 19).
// Tail: atomic accumulation (plain sums, m = 0 everywhere).
// ======================================================================
__global__ void __launch_bounds__(NTHR_, 2)
attn_main(const float* __restrict__ x, const int* __restrict__ mask,
          const float* __restrict__ queries)
{
    extern __shared__ float sm[];
    float* q_sh  = sm + NBUF_ * SM_TILE_F;     // [K][D]
    float* p_sh  = q_sh + SM_Q_F;              // [H][16][K]
    int*   mbase = (int*)(p_sh + SM_P_F);      // [NBUF][16]

    const int c    = blockIdx.x;
    const int tid  = threadIdx.x;
    const int w    = tid >> 5;                 // warp == head
    const int lane = tid & 31;
    const int row  = lane >> 1;                // phase-1 row (0..15)
    const int half = lane & 1;                 // which 32-dim half

    const int b = c / GB_;
    const int j = c % GB_;
    const int tstart = (j * TB_) / GB_;
    const int ntiles = ((j + 1) * TB_) / GB_ - tstart;

    const float* xb = x + ((long)b * T_ + (long)tstart * TROWS_) * D_;
    const int*   mb = mask + (long)b * T_ + tstart * TROWS_;

    // queries -> shared once
    #pragma unroll
    for (int i = tid; i < SM_Q_F/4; i += NTHR_)
        *reinterpret_cast<float4*>(q_sh + i*4) =
            *reinterpret_cast<const float4*>(queries + i*4);

    float  l[K_];
    float2 acc[K_];
    #pragma unroll
    for (int k = 0; k < K_; k++) { l[k] = 0.f; acc[k] = make_float2(0.f, 0.f); }

    // prologue: issue tiles 0 and 1
    issue_tile(xb, sm, mb, mbase, tid);
    CP_COMMIT();
    issue_tile(xb + (long)TROWS_*D_, sm + SM_TILE_F, mb + TROWS_, mbase + TROWS_, tid);
    CP_COMMIT();

    for (int tl = 0; tl < ntiles; tl++) {
        if (tl + 1 < ntiles) CP_WAIT1(); else CP_WAIT0();
        __syncthreads();   // tile tl visible; all warps done reading buf (tl-1)%3

        if (tl + 2 < ntiles) {
            int nb = (tl + 2) % NBUF_;
            issue_tile(xb + (long)(tl+2) * TROWS_ * D_, sm + nb * SM_TILE_F,
                       mb + (tl+2) * TROWS_, mbase + nb * TROWS_, tid);
            CP_COMMIT();
        }

        const float* tile = sm + (tl % NBUF_) * SM_TILE_F;
        const int*   msk  = mbase + (tl % NBUF_) * TROWS_;

        // ---- phase 1: lane pair = row; each lane does 32 dims ----
        float2 sk[K_];
        #pragma unroll
        for (int k = 0; k < K_; k++) sk[k] = make_float2(0.f, 0.f);
        const float* vrow = tile + row * TSTRIDE_ + w * HD_ + half * 32;
        const float* qh   = q_sh + w * HD_ + half * 32;
        #pragma unroll
        for (int i4 = 0; i4 < 8; i4++) {
            int j4 = (i4 + half) & 7;          // phase shift: conflict-free
            float4 v4 = *reinterpret_cast<const float4*>(vrow + j4 * 4);
            float2 va = make_float2(v4.x, v4.y);
            float2 vb = make_float2(v4.z, v4.w);
            #pragma unroll
            for (int k = 0; k < K_; k++) {
                float4 q4 = *reinterpret_cast<const float4*>(qh + k * D_ + j4 * 4);
                sk[k] = ffma2(va, make_float2(q4.x, q4.y), sk[k]);
                sk[k] = ffma2(vb, make_float2(q4.z, q4.w), sk[k]);
            }
        }
        const int mv = msk[row];
        float p[K_];
        #pragma unroll
        for (int k = 0; k < K_; k++) {
            float v = sk[k].x + sk[k].y;
            v += __shfl_xor_sync(0xffffffffu, v, 1);   // combine halves
            p[k] = (mv == 0) ? 0.f : __expf(v * 0.125f);
            l[k] += p[k];
        }
        if (half == 0)
            *reinterpret_cast<float4*>(p_sh + (w * TROWS_ + row) * K_) =
                make_float4(p[0], p[1], p[2], p[3]);
        __syncwarp();

        // ---- phase 2: lane owns d = {2*lane, 2*lane+1} of this head ----
        const float* base2 = tile + w * HD_ + 2 * lane;
        const float* pb    = p_sh + w * TROWS_ * K_;
        #pragma unroll
        for (int t = 0; t < TROWS_; t++) {
            float2 v2 = *reinterpret_cast<const float2*>(base2 + t * TSTRIDE_);
            float4 p4 = *reinterpret_cast<const float4*>(pb + t * K_);
            acc[0] = ffma2(v2, make_float2(p4.x, p4.x), acc[0]);
            acc[1] = ffma2(v2, make_float2(p4.y, p4.y), acc[1]);
            acc[2] = ffma2(v2, make_float2(p4.z, p4.z), acc[2]);
            acc[3] = ffma2(v2, make_float2(p4.w, p4.w), acc[3]);
        }
        // next iteration's __syncthreads protects buffers & p_sh
    }

    // ---- reduce l across lanes (each row counted twice -> *0.5) ----
    #pragma unroll
    for (int k = 0; k < K_; k++) {
        float v = l[k];
        #pragma unroll
        for (int off = 16; off > 0; off >>= 1)
            v += __shfl_xor_sync(0xffffffffu, v, off);
        l[k] = v * 0.5f;
    }

    // ---- atomic tail: plain sums across CTAs (m = 0 everywhere) ----
    if (lane == 0) {
        #pragma unroll
        for (int k = 0; k < K_; k++)
            atomicAdd(&g_lsum[((long)b * K_ + k) * H_ + w], l[k]);
    }
    #pragma unroll
    for (int k = 0; k < K_; k++) {
        float* dst = &g_pool[((long)b * K_ + k) * D_ + w * HD_ + 2 * lane];
        atomicAdd(dst,     acc[k].x);
        atomicAdd(dst + 1, acc[k].y);
    }
}

// ======================================================================
// Kernel 2: normalize pooled rows + linear projection.
// ======================================================================
__global__ void __launch_bounds__(256)
epi_k(const float* __restrict__ w_out, const float* __restrict__ b_out,
      float* __restrict__ out)
{
    __shared__ __align__(16) float ps[8][D_];
    __shared__ float slt[8][H_];
    const int rg  = blockIdx.x;             // rows rg*8..rg*8+7  (row = b*K + k)
    const int jg  = blockIdx.y;
    const int tid = threadIdx.x;

    if (tid < 64) {
        int r = tid >> 3, h = tid & 7;
        slt[r][h] = g_lsum[(long)(rg * 8 + r) * H_ + h];
    }
    __syncthreads();

    for (int i = tid; i < 8 * D_; i += 256) {
        int r = i >> 9, col = i & 511;
        ps[r][col] = g_pool[(long)(rg * 8 + r) * D_ + col] / slt[r][col >> 6];
    }
    __syncthreads();

    const int jl = tid & 63;
    const int rp = tid >> 6;                // rows rp*2, rp*2+1
    const int j  = jg * 64 + jl;
    const float* wr = w_out + (long)j * D_;

    float2 a0 = make_float2(0.f, 0.f), a1 = make_float2(0.f, 0.f);
    #pragma unroll 8
    for (int i4 = 0; i4 < D_/4; i4++) {
        float4 wv = *reinterpret_cast<const float4*>(wr + i4 * 4);
        float4 p0 = *reinterpret_cast<const float4*>(&ps[rp*2    ][i4*4]);
        float4 p1 = *reinterpret_cast<const float4*>(&ps[rp*2 + 1][i4*4]);
        a0 = ffma2(make_float2(wv.x, wv.y), make_float2(p0.x, p0.y), a0);
        a0 = ffma2(make_float2(wv.z, wv.w), make_float2(p0.z, p0.w), a0);
        a1 = ffma2(make_float2(wv.x, wv.y), make_float2(p1.x, p1.y), a1);
        a1 = ffma2(make_float2(wv.z, wv.w), make_float2(p1.z, p1.w), a1);
    }
    float bj = b_out[j];
    out[(long)(rg*8 + rp*2    ) * D_ + j] = bj + a0.x + a0.y;
    out[(long)(rg*8 + rp*2 + 1) * D_ + j] = bj + a1.x + a1.y;
}

// ======================================================================
extern "C" void kernel_launch(void* const* d_in, const int* in_sizes, int n_in,
                              void* d_out, int out_size)
{
    const float* x       = (const float*)d_in[0];
    const int*   mask    = (const int*)  d_in[1];
    const float* queries = (const float*)d_in[2];
    const float* w_out   = (const float*)d_in[3];
    const float* b_out   = (const float*)d_in[4];
    float* out = (float*)d_out;

    cudaFuncSetAttribute((const void*)attn_main,
                         cudaFuncAttributeMaxDynamicSharedMemorySize, SMEM_BYTES);

    zero_k<<<(B_*K_*D_ + 255) / 256, 256>>>();
    attn_main<<<G_, NTHR_, SMEM_BYTES>>>(x, mask, queries);
    epi_k<<<dim3(8, 8), 256>>>(w_out, b_out, out);
}

// round 8
// speedup vs baseline: 1.1798x; 1.1798x over previous
#include <cuda_runtime.h>
#include <cuda_bf16.h>
#include <math.h>

// Problem constants (fixed by reference)
#define B_      16
#define T_      8192
#define D_      512
#define H_      8
#define HD_     64
#define K_      4
#define TROWS_  16
#define TB_     (T_/TROWS_)       // 512 tiles per batch
#define NTHR_   256

// One balanced wave at 2 CTAs/SM on 152 SMs: 304 = 16 x 19
#define GB_     19
#define G_      (B_*GB_)

// Per-warp buffer: 16 rows x 68 floats (64 data + 4 pad; 17 chunks == 1 mod 8
// -> conflict-optimal LDS) + 16 mask ints. Two buffers per warp.
#define WSTR_    68
#define WBUF_F   (TROWS_*WSTR_ + TROWS_)   // 1104 floats = 4416 B (16B aligned)
#define SM_WARPS_F (H_*2*WBUF_F)           // 17664
#define SM_Q_F   (K_*D_)                   // 2048
#define SM_P_F   (H_*TROWS_*K_)            // 512
#define SMEM_BYTES ((SM_WARPS_F + SM_Q_F + SM_P_F)*4)   // 80896 B

// ---------------- device scratch (no allocations allowed) ----------------
__device__ __align__(16) float g_pool[B_*K_*D_];     // atomic accumulators
__device__ __align__(16) float g_lsum[B_*K_*H_];     // atomic denominators

// ---------------- packed fp32x2 FMA (Blackwell) ----------------
union F2U { float2 f; unsigned long long u; };
__device__ __forceinline__ float2 ffma2(float2 a, float2 b, float2 c) {
    F2U A, Bv, C, Dv;
    A.f = a; Bv.f = b; C.f = c;
    asm("fma.rn.f32x2 %0, %1, %2, %3;" : "=l"(Dv.u) : "l"(A.u), "l"(Bv.u), "l"(C.u));
    return Dv.f;
}

#define CP_COMMIT() asm volatile("cp.async.commit_group;")
#define CP_WAIT1()  asm volatile("cp.async.wait_group 1;")
#define CP_WAIT0()  asm volatile("cp.async.wait_group 0;")

__device__ __forceinline__ void cp16(float* dst_sh, const void* src) {
    unsigned d = (unsigned)__cvta_generic_to_shared(dst_sh);
    asm volatile("cp.async.cg.shared.global [%0], [%1], 16;" :: "r"(d), "l"(src));
}

// Per-warp: copy this head's 64-float slice of 16 rows (+ 16 mask ints).
// src = x row base already offset by w*HD_. 8 cp16 per lane, coalesced in
// 256B segments per half-warp.
__device__ __forceinline__ void issue_wtile(const float* __restrict__ src,
                                            float* __restrict__ dst,
                                            const int* __restrict__ msrc,
                                            int lane)
{
    #pragma unroll
    for (int i = 0; i < 8; i++) {
        int cchunk = lane + 32 * i;          // 0..255
        int row = cchunk >> 4;               // 0..15
        int ch  = cchunk & 15;               // 0..15
        cp16(dst + row * WSTR_ + ch * 4, src + (long)row * D_ + ch * 4);
    }
    if (lane < 4)
        cp16(dst + TROWS_ * WSTR_ + lane * 4, msrc + lane * 4);
}

// ======================================================================
// Kernel 0: zero the atomic accumulators
// ======================================================================
__global__ void zero_k()
{
    int i = blockIdx.x * 256 + threadIdx.x;
    if (i < B_*K_*D_) g_pool[i] = 0.f;
    if (i < B_*K_*H_) g_lsum[i] = 0.f;
}

// ======================================================================
// Kernel 1: warp-autonomous attention pooling, fixed softmax shift (m=0).
// Each warp = one head, streams its own head-slice through a private
// double-buffered smem slab. NO __syncthreads in the mainloop; 16
// independent warp pipelines per SM.
// ======================================================================
__global__ void __launch_bounds__(NTHR_, 2)
attn_main(const float* __restrict__ x, const int* __restrict__ mask,
          const float* __restrict__ queries)
{
    extern __shared__ float sm[];
    float* q_sh = sm + SM_WARPS_F;             // [K][512]
    float* p_sh = q_sh + SM_Q_F;               // [H][16][K]

    const int c    = blockIdx.x;
    const int tid  = threadIdx.x;
    const int w    = tid >> 5;                 // warp == head
    const int lane = tid & 31;
    const int row  = lane >> 1;                // phase-1 row (0..15)
    const int half = lane & 1;                 // which 32-dim half

    const int b = c / GB_;
    const int j = c % GB_;
    const int tstart = (j * TB_) / GB_;
    const int ntiles = ((j + 1) * TB_) / GB_ - tstart;

    // this warp's global sources (head slice) and private smem slab
    const float* xw = x + ((long)b * T_ + (long)tstart * TROWS_) * D_ + w * HD_;
    const int*   mw = mask + (long)b * T_ + tstart * TROWS_;
    float* wb = sm + w * 2 * WBUF_F;           // two private buffers

    // queries -> shared (block-cooperative, once)
    #pragma unroll
    for (int i = tid; i < SM_Q_F/4; i += NTHR_)
        *reinterpret_cast<float4*>(q_sh + i*4) =
            *reinterpret_cast<const float4*>(queries + i*4);

    // prologue: this warp issues its tiles 0 and 1
    issue_wtile(xw, wb, mw, lane);
    CP_COMMIT();
    issue_wtile(xw + (long)TROWS_ * D_, wb + WBUF_F, mw + TROWS_, lane);
    CP_COMMIT();

    __syncthreads();                           // q_sh visible (once, only here)

    float  l[K_];
    float2 acc[K_];
    #pragma unroll
    for (int k = 0; k < K_; k++) { l[k] = 0.f; acc[k] = make_float2(0.f, 0.f); }

    const float* qh  = q_sh + w * HD_ + half * 32;
    float*       p_w = p_sh + w * TROWS_ * K_;

    for (int tl = 0; tl < ntiles; tl++) {
        if (tl + 1 < ntiles) CP_WAIT1(); else CP_WAIT0();
        __syncwarp();                          // warp-scope visibility of tile tl

        float* tile = wb + (tl & 1) * WBUF_F;
        const int* msk = (const int*)(tile + TROWS_ * WSTR_);

        // ---- phase 1: lane pair = row; each lane does 32 dims ----
        float2 sk[K_];
        #pragma unroll
        for (int k = 0; k < K_; k++) sk[k] = make_float2(0.f, 0.f);
        const float* vrow = tile + row * WSTR_ + half * 32;
        #pragma unroll
        for (int i4 = 0; i4 < 8; i4++) {
            int j4 = (i4 + half) & 7;          // phase shift: conflict-free
            float4 v4 = *reinterpret_cast<const float4*>(vrow + j4 * 4);
            float2 va = make_float2(v4.x, v4.y);
            float2 vb = make_float2(v4.z, v4.w);
            #pragma unroll
            for (int k = 0; k < K_; k++) {
                float4 q4 = *reinterpret_cast<const float4*>(qh + k * D_ + j4 * 4);
                sk[k] = ffma2(va, make_float2(q4.x, q4.y), sk[k]);
                sk[k] = ffma2(vb, make_float2(q4.z, q4.w), sk[k]);
            }
        }
        const int mv = msk[row];
        float p[K_];
        #pragma unroll
        for (int k = 0; k < K_; k++) {
            float v = sk[k].x + sk[k].y;
            v += __shfl_xor_sync(0xffffffffu, v, 1);   // combine halves
            p[k] = (mv == 0) ? 0.f : __expf(v * 0.125f);
            l[k] += p[k];
        }
        if (half == 0)
            *reinterpret_cast<float4*>(p_w + row * K_) =
                make_float4(p[0], p[1], p[2], p[3]);
        __syncwarp();

        // ---- phase 2: lane owns d = {2*lane, 2*lane+1} of this head ----
        const float* base2 = tile + 2 * lane;
        #pragma unroll
        for (int t = 0; t < TROWS_; t++) {
            float2 v2 = *reinterpret_cast<const float2*>(base2 + t * WSTR_);
            float4 p4 = *reinterpret_cast<const float4*>(p_w + t * K_);
            acc[0] = ffma2(v2, make_float2(p4.x, p4.x), acc[0]);
            acc[1] = ffma2(v2, make_float2(p4.y, p4.y), acc[1]);
            acc[2] = ffma2(v2, make_float2(p4.z, p4.z), acc[2]);
            acc[3] = ffma2(v2, make_float2(p4.w, p4.w), acc[3]);
        }
        __syncwarp();                          // all lanes done reading buffer

        if (tl + 2 < ntiles) {
            issue_wtile(xw + (long)(tl + 2) * TROWS_ * D_,
                        wb + (tl & 1) * WBUF_F, mw + (tl + 2) * TROWS_, lane);
            CP_COMMIT();
        }
    }

    // ---- reduce l across lanes (each row counted twice -> *0.5) ----
    #pragma unroll
    for (int k = 0; k < K_; k++) {
        float v = l[k];
        #pragma unroll
        for (int off = 16; off > 0; off >>= 1)
            v += __shfl_xor_sync(0xffffffffu, v, off);
        l[k] = v * 0.5f;
    }

    // ---- atomic tail: plain sums across CTAs (m = 0 everywhere) ----
    if (lane == 0) {
        #pragma unroll
        for (int k = 0; k < K_; k++)
            atomicAdd(&g_lsum[((long)b * K_ + k) * H_ + w], l[k]);
    }
    #pragma unroll
    for (int k = 0; k < K_; k++) {
        float* dst = &g_pool[((long)b * K_ + k) * D_ + w * HD_ + 2 * lane];
        atomicAdd(dst,     acc[k].x);
        atomicAdd(dst + 1, acc[k].y);
    }
}

// ======================================================================
// Kernel 2: normalize pooled rows + linear projection.
// ======================================================================
__global__ void __launch_bounds__(256)
epi_k(const float* __restrict__ w_out, const float* __restrict__ b_out,
      float* __restrict__ out)
{
    __shared__ __align__(16) float ps[8][D_];
    __shared__ float slt[8][H_];
    const int rg  = blockIdx.x;             // rows rg*8..rg*8+7  (row = b*K + k)
    const int jg  = blockIdx.y;
    const int tid = threadIdx.x;

    if (tid < 64) {
        int r = tid >> 3, h = tid & 7;
        slt[r][h] = g_lsum[(long)(rg * 8 + r) * H_ + h];
    }
    __syncthreads();

    for (int i = tid; i < 8 * D_; i += 256) {
        int r = i >> 9, col = i & 511;
        ps[r][col] = g_pool[(long)(rg * 8 + r) * D_ + col] / slt[r][col >> 6];
    }
    __syncthreads();

    const int jl = tid & 63;
    const int rp = tid >> 6;                // rows rp*2, rp*2+1
    const int j  = jg * 64 + jl;
    const float* wr = w_out + (long)j * D_;

    float2 a0 = make_float2(0.f, 0.f), a1 = make_float2(0.f, 0.f);
    #pragma unroll 8
    for (int i4 = 0; i4 < D_/4; i4++) {
        float4 wv = *reinterpret_cast<const float4*>(wr + i4 * 4);
        float4 p0 = *reinterpret_cast<const float4*>(&ps[rp*2    ][i4*4]);
        float4 p1 = *reinterpret_cast<const float4*>(&ps[rp*2 + 1][i4*4]);
        a0 = ffma2(make_float2(wv.x, wv.y), make_float2(p0.x, p0.y), a0);
        a0 = ffma2(make_float2(wv.z, wv.w), make_float2(p0.z, p0.w), a0);
        a1 = ffma2(make_float2(wv.x, wv.y), make_float2(p1.x, p1.y), a1);
        a1 = ffma2(make_float2(wv.z, wv.w), make_float2(p1.z, p1.w), a1);
    }
    float bj = b_out[j];
    out[(long)(rg*8 + rp*2    ) * D_ + j] = bj + a0.x + a0.y;
    out[(long)(rg*8 + rp*2 + 1) * D_ + j] = bj + a1.x + a1.y;
}

// ======================================================================
extern "C" void kernel_launch(void* const* d_in, const int* in_sizes, int n_in,
                              void* d_out, int out_size)
{
    const float* x       = (const float*)d_in[0];
    const int*   mask    = (const int*)  d_in[1];
    const float* queries = (const float*)d_in[2];
    const float* w_out   = (const float*)d_in[3];
    const float* b_out   = (const float*)d_in[4];
    float* out = (float*)d_out;

    cudaFuncSetAttribute((const void*)attn_main,
                         cudaFuncAttributeMaxDynamicSharedMemorySize, SMEM_BYTES);

    zero_k<<<(B_*K_*D_ + 255) / 256, 256>>>();
    attn_main<<<G_, NTHR_, SMEM_BYTES>>>(x, mask, queries);
    epi_k<<<dim3(8, 8), 256>>>(w_out, b_out, out);
}

// round 9
// speedup vs baseline: 1.2359x; 1.0476x over previous
#include <cuda_runtime.h>
#include <cuda_bf16.h>
#include <math.h>

// Problem constants (fixed by reference)
#define B_      16
#define T_      8192
#define D_      512
#define H_      8
#define HD_     64
#define K_      4
#define TR_     8                 // rows per tile
#define TB_     (T_/TR_)          // 1024 tiles per batch
#define NTHR_   256
#define NBUF_   4

// One balanced wave at 2 CTAs/SM on 152 SMs: 304 = 16 x 19
#define GB_     19
#define G_      (B_*GB_)

// Per-warp buffer: 8 rows x 68 floats (64 data + 4 pad) + 8 mask ints.
#define WSTR_    68
#define WBUF_F   (TR_*WSTR_ + 8)          // 552 floats = 2208 B (16B aligned)
#define SM_WARPS_F (H_*NBUF_*WBUF_F)      // 17664 floats
#define SM_P_F   (H_*TR_*K_)              // 256 floats
#define SMEM_BYTES ((SM_WARPS_F + SM_P_F)*4)   // 71680 B

// ---------------- device scratch (no allocations allowed) ----------------
__device__ __align__(16) float g_pool[B_*K_*D_];     // atomic accumulators
__device__ __align__(16) float g_lsum[B_*K_*H_];     // atomic denominators

// ---------------- packed fp32x2 FMA (Blackwell) ----------------
union F2U { float2 f; unsigned long long u; };
__device__ __forceinline__ float2 ffma2(float2 a, float2 b, float2 c) {
    F2U A, Bv, C, Dv;
    A.f = a; Bv.f = b; C.f = c;
    asm("fma.rn.f32x2 %0, %1, %2, %3;" : "=l"(Dv.u) : "l"(A.u), "l"(Bv.u), "l"(C.u));
    return Dv.f;
}

#define CP_COMMIT() asm volatile("cp.async.commit_group;")
#define CP_WAIT2()  asm volatile("cp.async.wait_group 2;")
#define CP_WAIT1()  asm volatile("cp.async.wait_group 1;")
#define CP_WAIT0()  asm volatile("cp.async.wait_group 0;")

__device__ __forceinline__ void cp16(float* dst_sh, const void* src) {
    unsigned d = (unsigned)__cvta_generic_to_shared(dst_sh);
    asm volatile("cp.async.cg.shared.global [%0], [%1], 16;" :: "r"(d), "l"(src));
}

// Per-warp: copy this head's 64-float slice of 8 rows (+ 8 mask ints).
__device__ __forceinline__ void issue_wtile(const float* __restrict__ src,
                                            float* __restrict__ dst,
                                            const int* __restrict__ msrc,
                                            int lane)
{
    #pragma unroll
    for (int i = 0; i < 4; i++) {
        int cchunk = lane + 32 * i;          // 0..127
        int row = cchunk >> 4;               // 0..7
        int ch  = cchunk & 15;               // 0..15
        cp16(dst + row * WSTR_ + ch * 4, src + (long)row * D_ + ch * 4);
    }
    if (lane < 2)
        cp16(dst + TR_ * WSTR_ + lane * 4, msrc + lane * 4);
}

// ======================================================================
// Kernel 0: zero the atomic accumulators
// ======================================================================
__global__ void zero_k()
{
    int i = blockIdx.x * 256 + threadIdx.x;
    if (i < B_*K_*D_) g_pool[i] = 0.f;
    if (i < B_*K_*H_) g_lsum[i] = 0.f;
}

// ======================================================================
// Kernel 1: warp-autonomous attention pooling, fixed softmax shift (m=0).
// lane = (row, k): each lane owns one full (row, query) dot product.
// q register-resident; NO shuffles / q-loads in the mainloop.
// NBUF=4 private buffers per warp -> 3 tiles in flight.
// ======================================================================
__global__ void __launch_bounds__(NTHR_, 2)
attn_main(const float* __restrict__ x, const int* __restrict__ mask,
          const float* __restrict__ queries)
{
    extern __shared__ float sm[];
    float* p_sh = sm + SM_WARPS_F;             // [H][8][K]

    const int c    = blockIdx.x;
    const int tid  = threadIdx.x;
    const int w    = tid >> 5;                 // warp == head
    const int lane = tid & 31;
    const int row  = lane >> 2;                // 0..7
    const int k_ln = lane & 3;                 // this lane's query index

    const int b = c / GB_;
    const int j = c % GB_;
    const int tstart = (j * TB_) / GB_;
    const int ntiles = ((j + 1) * TB_) / GB_ - tstart;   // ~53-54, always >= 4

    const float* xw = x + ((long)b * T_ + (long)tstart * TR_) * D_ + w * HD_;
    const int*   mw = mask + (long)b * T_ + tstart * TR_;
    float* wb  = sm + w * NBUF_ * WBUF_F;      // private buffers
    float* p_w = p_sh + w * TR_ * K_;

    // ---- q -> registers: this lane's query row, this head's 64 dims ----
    float4 q[16];
    const float4* qsrc = reinterpret_cast<const float4*>(
                             queries + (long)k_ln * D_ + w * HD_);
    #pragma unroll
    for (int i = 0; i < 16; i++) q[i] = __ldg(qsrc + i);

    float  l = 0.f;
    float2 acc[K_];
    #pragma unroll
    for (int k = 0; k < K_; k++) acc[k] = make_float2(0.f, 0.f);

    // prologue: 3 tiles in flight
    #pragma unroll
    for (int i = 0; i < 3; i++) {
        issue_wtile(xw + (long)i * TR_ * D_, wb + i * WBUF_F, mw + i * TR_, lane);
        CP_COMMIT();
    }

    for (int tl = 0; tl < ntiles; tl++) {
        int pend = ntiles - (tl + 1); if (pend > 2) pend = 2;
        if (pend == 2) CP_WAIT2(); else if (pend == 1) CP_WAIT1(); else CP_WAIT0();
        __syncwarp();

        float* tile = wb + (tl & (NBUF_-1)) * WBUF_F;
        const int* msk = (const int*)(tile + TR_ * WSTR_);

        // ---- phase 1: full 64-dim dot, q in regs, v quad-broadcast ----
        float2 sk = make_float2(0.f, 0.f);
        const float* vrow = tile + row * WSTR_;
        #pragma unroll
        for (int i4 = 0; i4 < 16; i4++) {
            float4 v4 = *reinterpret_cast<const float4*>(vrow + i4 * 4);
            sk = ffma2(make_float2(v4.x, v4.y), make_float2(q[i4].x, q[i4].y), sk);
            sk = ffma2(make_float2(v4.z, v4.w), make_float2(q[i4].z, q[i4].w), sk);
        }
        float p = (msk[row] == 0) ? 0.f : __expf((sk.x + sk.y) * 0.125f);
        l += p;
        p_w[lane] = p;                         // [row][k] contiguous, conflict-free
        __syncwarp();

        // ---- phase 2: lane owns d = {2*lane, 2*lane+1} of this head ----
        const float* base2 = tile + 2 * lane;
        #pragma unroll
        for (int t = 0; t < TR_; t++) {
            float2 v2 = *reinterpret_cast<const float2*>(base2 + t * WSTR_);
            float4 p4 = *reinterpret_cast<const float4*>(p_w + t * K_);
            acc[0] = ffma2(v2, make_float2(p4.x, p4.x), acc[0]);
            acc[1] = ffma2(v2, make_float2(p4.y, p4.y), acc[1]);
            acc[2] = ffma2(v2, make_float2(p4.z, p4.z), acc[2]);
            acc[3] = ffma2(v2, make_float2(p4.w, p4.w), acc[3]);
        }
        __syncwarp();                          // lanes done reading buffer & p_w

        if (tl + 3 < ntiles) {
            issue_wtile(xw + (long)(tl + 3) * TR_ * D_,
                        wb + ((tl + 3) & (NBUF_-1)) * WBUF_F,
                        mw + (tl + 3) * TR_, lane);
            CP_COMMIT();
        }
    }

    // ---- reduce l over rows (lanes sharing k = lane&3) ----
    l += __shfl_xor_sync(0xffffffffu, l, 4);
    l += __shfl_xor_sync(0xffffffffu, l, 8);
    l += __shfl_xor_sync(0xffffffffu, l, 16);

    // ---- atomic tail: plain sums across CTAs (m = 0 everywhere) ----
    if (lane < K_)
        atomicAdd(&g_lsum[((long)b * K_ + lane) * H_ + w], l);
    #pragma unroll
    for (int k = 0; k < K_; k++) {
        float* dst = &g_pool[((long)b * K_ + k) * D_ + w * HD_ + 2 * lane];
        atomicAdd(dst,     acc[k].x);
        atomicAdd(dst + 1, acc[k].y);
    }
}

// ======================================================================
// Kernel 2: normalize pooled rows + linear projection.
// ======================================================================
__global__ void __launch_bounds__(256)
epi_k(const float* __restrict__ w_out, const float* __restrict__ b_out,
      float* __restrict__ out)
{
    __shared__ __align__(16) float ps[8][D_];
    __shared__ float slt[8][H_];
    const int rg  = blockIdx.x;             // rows rg*8..rg*8+7  (row = b*K + k)
    const int jg  = blockIdx.y;
    const int tid = threadIdx.x;

    if (tid < 64) {
        int r = tid >> 3, h = tid & 7;
        slt[r][h] = g_lsum[(long)(rg * 8 + r) * H_ + h];
    }
    __syncthreads();

    for (int i = tid; i < 8 * D_; i += 256) {
        int r = i >> 9, col = i & 511;
        ps[r][col] = g_pool[(long)(rg * 8 + r) * D_ + col] / slt[r][col >> 6];
    }
    __syncthreads();

    const int jl = tid & 63;
    const int rp = tid >> 6;                // rows rp*2, rp*2+1
    const int j  = jg * 64 + jl;
    const float* wr = w_out + (long)j * D_;

    float2 a0 = make_float2(0.f, 0.f), a1 = make_float2(0.f, 0.f);
    #pragma unroll 8
    for (int i4 = 0; i4 < D_/4; i4++) {
        float4 wv = *reinterpret_cast<const float4*>(wr + i4 * 4);
        float4 p0 = *reinterpret_cast<const float4*>(&ps[rp*2    ][i4*4]);
        float4 p1 = *reinterpret_cast<const float4*>(&ps[rp*2 + 1][i4*4]);
        a0 = ffma2(make_float2(wv.x, wv.y), make_float2(p0.x, p0.y), a0);
        a0 = ffma2(make_float2(wv.z, wv.w), make_float2(p0.z, p0.w), a0);
        a1 = ffma2(make_float2(wv.x, wv.y), make_float2(p1.x, p1.y), a1);
        a1 = ffma2(make_float2(wv.z, wv.w), make_float2(p1.z, p1.w), a1);
    }
    float bj = b_out[j];
    out[(long)(rg*8 + rp*2    ) * D_ + j] = bj + a0.x + a0.y;
    out[(long)(rg*8 + rp*2 + 1) * D_ + j] = bj + a1.x + a1.y;
}

// ======================================================================
extern "C" void kernel_launch(void* const* d_in, const int* in_sizes, int n_in,
                              void* d_out, int out_size)
{
    const float* x       = (const float*)d_in[0];
    const int*   mask    = (const int*)  d_in[1];
    const float* queries = (const float*)d_in[2];
    const float* w_out   = (const float*)d_in[3];
    const float* b_out   = (const float*)d_in[4];
    float* out = (float*)d_out;

    cudaFuncSetAttribute((const void*)attn_main,
                         cudaFuncAttributeMaxDynamicSharedMemorySize, SMEM_BYTES);

    zero_k<<<(B_*K_*D_ + 255) / 256, 256>>>();
    attn_main<<<G_, NTHR_, SMEM_BYTES>>>(x, mask, queries);
    epi_k<<<dim3(8, 8), 256>>>(w_out, b_out, out);
}

// round 10
// speedup vs baseline: 1.2369x; 1.0008x over previous
#include <cuda_runtime.h>
#include <cuda_bf16.h>
#include <math.h>

// Problem constants (fixed by reference)
#define B_      16
#define T_      8192
#define D_      512
#define H_      8
#define HD_     64
#define K_      4
#define TR_     8                 // rows per tile
#define TB_     (T_/TR_)          // 1024 tiles per batch
#define NTHR_   256
#define NBUF_   4

// One balanced wave at 2 CTAs/SM on 152 SMs: 304 = 16 x 19
#define GB_     19
#define G_      (B_*GB_)

// Per-warp buffer: 8 rows x 68 floats (64 data + 4 pad) + 8 mask ints.
#define WSTR_    68
#define WBUF_F   (TR_*WSTR_ + 8)          // 552 floats = 2208 B (16B aligned)
#define SM_WARPS_F (H_*NBUF_*WBUF_F)      // 17664 floats
#define SM_P_F   (H_*TR_*K_)              // 256 floats
#define SMEM_BYTES ((SM_WARPS_F + SM_P_F)*4)   // 71680 B

// ---------------- device scratch (no allocations allowed) ----------------
__device__ __align__(16) float g_pool[B_*K_*D_];     // atomic accumulators
__device__ __align__(16) float g_lsum[B_*K_*H_];     // atomic denominators

// ---------------- packed fp32x2 FMA (Blackwell) ----------------
union F2U { float2 f; unsigned long long u; };
__device__ __forceinline__ float2 ffma2(float2 a, float2 b, float2 c) {
    F2U A, Bv, C, Dv;
    A.f = a; Bv.f = b; C.f = c;
    asm("fma.rn.f32x2 %0, %1, %2, %3;" : "=l"(Dv.u) : "l"(A.u), "l"(Bv.u), "l"(C.u));
    return Dv.f;
}

#define CP_COMMIT() asm volatile("cp.async.commit_group;")
#define CP_WAIT2()  asm volatile("cp.async.wait_group 2;")
#define CP_WAIT1()  asm volatile("cp.async.wait_group 1;")
#define CP_WAIT0()  asm volatile("cp.async.wait_group 0;")

__device__ __forceinline__ void cp16(float* dst_sh, const void* src) {
    unsigned d = (unsigned)__cvta_generic_to_shared(dst_sh);
    asm volatile("cp.async.cg.shared.global [%0], [%1], 16;" :: "r"(d), "l"(src));
}

// Per-warp: copy this head's 64-float slice of 8 rows (+ 8 mask ints).
__device__ __forceinline__ void issue_wtile(const float* __restrict__ src,
                                            float* __restrict__ dst,
                                            const int* __restrict__ msrc,
                                            int lane)
{
    #pragma unroll
    for (int i = 0; i < 4; i++) {
        int cchunk = lane + 32 * i;          // 0..127
        int row = cchunk >> 4;               // 0..7
        int ch  = cchunk & 15;               // 0..15
        cp16(dst + row * WSTR_ + ch * 4, src + (long)row * D_ + ch * 4);
    }
    if (lane < 2)
        cp16(dst + TR_ * WSTR_ + lane * 4, msrc + lane * 4);
}

// ======================================================================
// Kernel 0: zero the atomic accumulators
// ======================================================================
__global__ void zero_k()
{
    int i = blockIdx.x * 256 + threadIdx.x;
    if (i < B_*K_*D_) g_pool[i] = 0.f;
    if (i < B_*K_*H_) g_lsum[i] = 0.f;
}

// ======================================================================
// Kernel 1: warp-autonomous attention pooling, fixed softmax shift (m=0).
// lane = (row, k). Phase-1 dot product now uses 4 INDEPENDENT partial
// accumulators (critical path 128 -> ~32 cyc per tile).
// ======================================================================
__global__ void __launch_bounds__(NTHR_, 2)
attn_main(const float* __restrict__ x, const int* __restrict__ mask,
          const float* __restrict__ queries)
{
    extern __shared__ float sm[];
    float* p_sh = sm + SM_WARPS_F;             // [H][8][K]

    const int c    = blockIdx.x;
    const int tid  = threadIdx.x;
    const int w    = tid >> 5;                 // warp == head
    const int lane = tid & 31;
    const int row  = lane >> 2;                // 0..7
    const int k_ln = lane & 3;                 // this lane's query index

    const int b = c / GB_;
    const int j = c % GB_;
    const int tstart = (j * TB_) / GB_;
    const int ntiles = ((j + 1) * TB_) / GB_ - tstart;   // ~53-54, always >= 4

    const float* xw = x + ((long)b * T_ + (long)tstart * TR_) * D_ + w * HD_;
    const int*   mw = mask + (long)b * T_ + tstart * TR_;
    float* wb  = sm + w * NBUF_ * WBUF_F;      // private buffers
    float* p_w = p_sh + w * TR_ * K_;

    // ---- q -> registers: this lane's query row, this head's 64 dims ----
    float4 q[16];
    const float4* qsrc = reinterpret_cast<const float4*>(
                             queries + (long)k_ln * D_ + w * HD_);
    #pragma unroll
    for (int i = 0; i < 16; i++) q[i] = __ldg(qsrc + i);

    float  l = 0.f;
    float2 acc[K_];
    #pragma unroll
    for (int k = 0; k < K_; k++) acc[k] = make_float2(0.f, 0.f);

    // prologue: 3 tiles in flight
    #pragma unroll
    for (int i = 0; i < 3; i++) {
        issue_wtile(xw + (long)i * TR_ * D_, wb + i * WBUF_F, mw + i * TR_, lane);
        CP_COMMIT();
    }

    for (int tl = 0; tl < ntiles; tl++) {
        int pend = ntiles - (tl + 1); if (pend > 2) pend = 2;
        if (pend == 2) CP_WAIT2(); else if (pend == 1) CP_WAIT1(); else CP_WAIT0();
        __syncwarp();

        float* tile = wb + (tl & (NBUF_-1)) * WBUF_F;
        const int* msk = (const int*)(tile + TR_ * WSTR_);

        // ---- phase 1: 64-dim dot with 4 independent partial sums ----
        float2 s0 = make_float2(0.f, 0.f), s1 = make_float2(0.f, 0.f);
        float2 s2 = make_float2(0.f, 0.f), s3 = make_float2(0.f, 0.f);
        const float* vrow = tile + row * WSTR_;
        #pragma unroll
        for (int g = 0; g < 4; g++) {          // 4 groups of 4 float4 chunks
            float4 va = *reinterpret_cast<const float4*>(vrow + (g*4+0) * 4);
            float4 vb = *reinterpret_cast<const float4*>(vrow + (g*4+1) * 4);
            float4 vc = *reinterpret_cast<const float4*>(vrow + (g*4+2) * 4);
            float4 vd = *reinterpret_cast<const float4*>(vrow + (g*4+3) * 4);
            s0 = ffma2(make_float2(va.x, va.y), make_float2(q[g*4+0].x, q[g*4+0].y), s0);
            s1 = ffma2(make_float2(va.z, va.w), make_float2(q[g*4+0].z, q[g*4+0].w), s1);
            s2 = ffma2(make_float2(vb.x, vb.y), make_float2(q[g*4+1].x, q[g*4+1].y), s2);
            s3 = ffma2(make_float2(vb.z, vb.w), make_float2(q[g*4+1].z, q[g*4+1].w), s3);
            s0 = ffma2(make_float2(vc.x, vc.y), make_float2(q[g*4+2].x, q[g*4+2].y), s0);
            s1 = ffma2(make_float2(vc.z, vc.w), make_float2(q[g*4+2].z, q[g*4+2].w), s1);
            s2 = ffma2(make_float2(vd.x, vd.y), make_float2(q[g*4+3].x, q[g*4+3].y), s2);
            s3 = ffma2(make_float2(vd.z, vd.w), make_float2(q[g*4+3].z, q[g*4+3].w), s3);
        }
        float2 t01 = make_float2(s0.x + s1.x, s0.y + s1.y);
        float2 t23 = make_float2(s2.x + s3.x, s2.y + s3.y);
        float  v   = (t01.x + t23.x) + (t01.y + t23.y);
        float p = (msk[row] == 0) ? 0.f : __expf(v * 0.125f);
        l += p;
        p_w[lane] = p;                         // [row][k] contiguous, conflict-free
        __syncwarp();

        // ---- phase 2: lane owns d = {2*lane, 2*lane+1} of this head ----
        const float* base2 = tile + 2 * lane;
        #pragma unroll
        for (int t = 0; t < TR_; t++) {
            float2 v2 = *reinterpret_cast<const float2*>(base2 + t * WSTR_);
            float4 p4 = *reinterpret_cast<const float4*>(p_w + t * K_);
            acc[0] = ffma2(v2, make_float2(p4.x, p4.x), acc[0]);
            acc[1] = ffma2(v2, make_float2(p4.y, p4.y), acc[1]);
            acc[2] = ffma2(v2, make_float2(p4.z, p4.z), acc[2]);
            acc[3] = ffma2(v2, make_float2(p4.w, p4.w), acc[3]);
        }
        __syncwarp();                          // lanes done reading buffer & p_w

        if (tl + 3 < ntiles) {
            issue_wtile(xw + (long)(tl + 3) * TR_ * D_,
                        wb + ((tl + 3) & (NBUF_-1)) * WBUF_F,
                        mw + (tl + 3) * TR_, lane);
            CP_COMMIT();
        }
    }

    // ---- reduce l over rows (lanes sharing k = lane&3) ----
    l += __shfl_xor_sync(0xffffffffu, l, 4);
    l += __shfl_xor_sync(0xffffffffu, l, 8);
    l += __shfl_xor_sync(0xffffffffu, l, 16);

    // ---- atomic tail: plain sums across CTAs (m = 0 everywhere) ----
    if (lane < K_)
        atomicAdd(&g_lsum[((long)b * K_ + lane) * H_ + w], l);
    #pragma unroll
    for (int k = 0; k < K_; k++) {
        float* dst = &g_pool[((long)b * K_ + k) * D_ + w * HD_ + 2 * lane];
        atomicAdd(dst,     acc[k].x);
        atomicAdd(dst + 1, acc[k].y);
    }
}

// ======================================================================
// Kernel 2: normalize pooled rows + linear projection.
// ======================================================================
__global__ void __launch_bounds__(256)
epi_k(const float* __restrict__ w_out, const float* __restrict__ b_out,
      float* __restrict__ out)
{
    __shared__ __align__(16) float ps[8][D_];
    __shared__ float slt[8][H_];
    const int rg  = blockIdx.x;             // rows rg*8..rg*8+7  (row = b*K + k)
    const int jg  = blockIdx.y;
    const int tid = threadIdx.x;

    if (tid < 64) {
        int r = tid >> 3, h = tid & 7;
        slt[r][h] = g_lsum[(long)(rg * 8 + r) * H_ + h];
    }
    __syncthreads();

    for (int i = tid; i < 8 * D_; i += 256) {
        int r = i >> 9, col = i & 511;
        ps[r][col] = g_pool[(long)(rg * 8 + r) * D_ + col] / slt[r][col >> 6];
    }
    __syncthreads();

    const int jl = tid & 63;
    const int rp = tid >> 6;                // rows rp*2, rp*2+1
    const int j  = jg * 64 + jl;
    const float* wr = w_out + (long)j * D_;

    float2 a0 = make_float2(0.f, 0.f), a1 = make_float2(0.f, 0.f);
    #pragma unroll 8
    for (int i4 = 0; i4 < D_/4; i4++) {
        float4 wv = *reinterpret_cast<const float4*>(wr + i4 * 4);
        float4 p0 = *reinterpret_cast<const float4*>(&ps[rp*2    ][i4*4]);
        float4 p1 = *reinterpret_cast<const float4*>(&ps[rp*2 + 1][i4*4]);
        a0 = ffma2(make_float2(wv.x, wv.y), make_float2(p0.x, p0.y), a0);
        a0 = ffma2(make_float2(wv.z, wv.w), make_float2(p0.z, p0.w), a0);
        a1 = ffma2(make_float2(wv.x, wv.y), make_float2(p1.x, p1.y), a1);
        a1 = ffma2(make_float2(wv.z, wv.w), make_float2(p1.z, p1.w), a1);
    }
    float bj = b_out[j];
    out[(long)(rg*8 + rp*2    ) * D_ + j] = bj + a0.x + a0.y;
    out[(long)(rg*8 + rp*2 + 1) * D_ + j] = bj + a1.x + a1.y;
}

// ======================================================================
extern "C" void kernel_launch(void* const* d_in, const int* in_sizes, int n_in,
                              void* d_out, int out_size)
{
    const float* x       = (const float*)d_in[0];
    const int*   mask    = (const int*)  d_in[1];
    const float* queries = (const float*)d_in[2];
    const float* w_out   = (const float*)d_in[3];
    const float* b_out   = (const float*)d_in[4];
    float* out = (float*)d_out;

    cudaFuncSetAttribute((const void*)attn_main,
                         cudaFuncAttributeMaxDynamicSharedMemorySize, SMEM_BYTES);

    zero_k<<<(B_*K_*D_ + 255) / 256, 256>>>();
    attn_main<<<G_, NTHR_, SMEM_BYTES>>>(x, mask, queries);
    epi_k<<<dim3(8, 8), 256>>>(w_out, b_out, out);
}